// round 17
// baseline (speedup 1.0000x reference)
#include <cuda_runtime.h>
#include <cstdint>
#include <cstddef>

#define BB   256
#define SS   64
#define HH   128
#define TT   63
#define MT   16128   // TT*BB
#define MS   16384   // BB*SS

#define C2E  2.8853900817779268f   // 2*log2(e): tanh(x) = 1 - 2/(2^(C2E*x)+1)

// ---------------- scratch ----------------
__device__ float  g_PA  [MS * 128];   // scaled by C2E
__device__ float  g_PP  [MS * 128];   // scaled by C2E
__device__ float  g_Hall[MT * 128];
__device__ float  g_HA2 [MT * 128];   // scaled by C2E
__device__ float  g_CTX [MT * 128];
__device__ float  g_FP2 [MT * 128];   // scaled by C2E
__device__ float  g_ZB  [BB * 128];   // scaled by C2E
__device__ float  g_W12 [384 * 128];
__device__ float  g_Wc  [384 * 128];
__device__ float  g_A0[384], g_A1[384], g_C0[384];
__device__ float  g_E0[128], g_E1[128];        // scaled by C2E
__device__ float  g_BB2[128], g_ZBIAS[128];    // ZBIAS scaled by C2E
__device__ float  g_VAS[1], g_VPS[1];          // sum(v_a), sum(vp)
__device__ float2 g_XY [MT];
__device__ int    g_pos[MS];

// ---------------- fast primitives ----------------
__device__ __forceinline__ float ex2f(float x) {
    float r; asm("ex2.approx.f32 %0, %1;" : "=f"(r) : "f"(x)); return r;
}
__device__ __forceinline__ float rcpf(float x) {
    float r; asm("rcp.approx.f32 %0, %1;" : "=f"(r) : "f"(x)); return r;
}
#define FMA2(out, a, b, c) \
    asm("fma.rn.f32x2 %0, %1, %2, %3;" : "=l"(out) : "l"(a), "l"(b), "l"(c))
#define MUL2(out, a, b) \
    asm("mul.rn.f32x2 %0, %1, %2;" : "=l"(out) : "l"(a), "l"(b))
#define ADD2(out, a, b) \
    asm("add.rn.f32x2 %0, %1, %2;" : "=l"(out) : "l"(a), "l"(b))
__device__ __forceinline__ float2 upk(uint64_t v) {
    float2 r; asm("mov.b64 {%0,%1}, %2;" : "=f"(r.x), "=f"(r.y) : "l"(v)); return r;
}
__device__ __forceinline__ uint64_t pack2(float x, float y) {
    uint64_t r; asm("mov.b64 %0, {%1,%2};" : "=l"(r) : "f"(x), "f"(y)); return r;
}

// GRU-side activations (small volume)
__device__ __forceinline__ float tanh_f(float x) {
    float xc = fminf(fmaxf(x, -9.0f), 9.0f);
    float e = __expf(2.0f * xc);
    return __fdividef(e - 1.0f, e + 1.0f);
}
__device__ __forceinline__ float sigmoid_f(float x) {
    float xc = fminf(fmaxf(x, -30.0f), 30.0f);
    float e = __expf(xc);
    return __fdividef(e, e + 1.0f);
}

__device__ __forceinline__ float warp_sum(float v) {
#pragma unroll
    for (int o = 16; o; o >>= 1) v += __shfl_xor_sync(0xFFFFFFFFu, v, o);
    return v;
}

// Packed: acc2 += (-va)*y where y -> -rcp(2^a+1) via magic seed + 2 Newton.
__device__ __forceinline__ void term2(uint64_t a2, uint64_t van2, uint64_t two2,
                                      uint64_t& acc2) {
    float2 a = upk(a2);
    float elo = ex2f(a.x), ehi = ex2f(a.y);
    float dlo = elo + 1.0f, dhi = ehi + 1.0f;
    float ylo = __int_as_float((0x7EF311C3 - __float_as_int(dlo)) | 0x80000000);
    float yhi = __int_as_float((0x7EF311C3 - __float_as_int(dhi)) | 0x80000000);
    uint64_t y2 = pack2(ylo, yhi);
    uint64_t d2 = pack2(dlo, dhi);
    uint64_t u2;
    FMA2(u2, d2, y2, two2); MUL2(y2, y2, u2);
    FMA2(u2, d2, y2, two2); MUL2(y2, y2, u2);
    FMA2(acc2, van2, y2, acc2);
}

// ---------------- init + prep1 merged (block-range routed) ----------------
__global__ void __launch_bounds__(256) k_initprep(const float* __restrict__ inst,
                                                  const int* __restrict__ sol,
                                                  float* __restrict__ out,
                                                  const float* __restrict__ W_emb,
                                                  const float* __restrict__ b_emb,
                                                  const float* __restrict__ W_ih,
                                                  const float* __restrict__ b_ih,
                                                  const float* __restrict__ b1,
                                                  const float* __restrict__ W2,
                                                  const float* __restrict__ v_a,
                                                  const float* __restrict__ vp) {
    if (blockIdx.x < 128) {
        int i = blockIdx.x * blockDim.x + threadIdx.x;
        if (i < MT) {
            int t = i >> 8, b = i & 255;
            int s = sol[(b << 6) + t];
            g_XY[i] = reinterpret_cast<const float2*>(inst)[(b << 6) + s];
        } else if (i < MT + MS) {
            int e = i - MT;
            int b = e >> 6;
            int s = sol[e];
            g_pos[(b << 6) + s] = e & 63;
        } else if (i < MT + MS + BB) {
            int b = i - (MT + MS);
            out[b << 6] = (float)sol[b << 6];
        }
        return;
    }
    int task = (blockIdx.x - 128) * 8 + (threadIdx.x >> 5);
    int l = threadIdx.x & 31;
    if (task < 384) {
        int j = task;
        float4 w4 = reinterpret_cast<const float4*>(W_ih + (size_t)j * 128)[l];
        float4 e0 = reinterpret_cast<const float4*>(W_emb)[l];
        float4 e1 = reinterpret_cast<const float4*>(W_emb + 128)[l];
        float4 be = reinterpret_cast<const float4*>(b_emb)[l];
        float a0 = w4.x * e0.x + w4.y * e0.y + w4.z * e0.z + w4.w * e0.w;
        float a1 = w4.x * e1.x + w4.y * e1.y + w4.z * e1.z + w4.w * e1.w;
        float c0 = w4.x * be.x + w4.y * be.y + w4.z * be.z + w4.w * be.w;
        a0 = warp_sum(a0); a1 = warp_sum(a1); c0 = warp_sum(c0);
        if (l == 0) { g_A0[j] = a0; g_A1[j] = a1; g_C0[j] = c0 + b_ih[j]; }
    } else if (task < 512) {
        int j = task - 384;
        float bb = 0.f;
#pragma unroll
        for (int i = 0; i < 8; i++) {
            int m = l + 32 * i;
            bb = fmaf(b1[m], W2[m * 128 + j], bb);
        }
        bb = warp_sum(bb);
        if (l == 0) g_BB2[j] = bb;
    } else if (task < 514) {
        const float* v = (task == 512) ? v_a : vp;
        float s = v[l] + v[l + 32] + v[l + 64] + v[l + 96];
        s = warp_sum(s);
        if (l == 0) { if (task == 512) g_VAS[0] = s; else g_VPS[0] = s; }
    }
}

// ---------------- prep2 (needs Wc, BB2) ----------------
__global__ void __launch_bounds__(256) k_prep2(const float* __restrict__ W_emb,
                                               const float* __restrict__ b_emb,
                                               const float* __restrict__ Wp) {
    int task = blockIdx.x * 8 + (threadIdx.x >> 5);
    int l = threadIdx.x & 31;
    int j = task & 127;
    int kind = task >> 7;
    if (kind < 2) {
        const float* src = (kind == 0) ? W_emb : (W_emb + 128);
        float acc = 0.f;
#pragma unroll
        for (int i = 0; i < 4; i++) {
            int k = l + 32 * i;
            acc = fmaf(src[k], g_Wc[(size_t)(256 + k) * 128 + j], acc);
        }
        acc = warp_sum(acc) * C2E;
        if (l == 0) { if (kind == 0) g_E0[j] = acc; else g_E1[j] = acc; }
    } else {
        float acc = 0.f;
#pragma unroll
        for (int i = 0; i < 4; i++) {
            int k = l + 32 * i;
            acc = fmaf(b_emb[k], g_Wc[(size_t)(256 + k) * 128 + j], acc);
            acc = fmaf(g_BB2[k], Wp[(size_t)(128 + k) * 128 + j], acc);
        }
        acc = warp_sum(acc) * C2E;
        if (l == 0) g_ZBIAS[j] = acc;
    }
}

// ---------------- fp32 GEMM 64x64 (small side-stream matrices) ----------------
__global__ void __launch_bounds__(256) gemm64(const float* __restrict__ A, int lda,
                                              const float* __restrict__ B, int ldb,
                                              const float* __restrict__ bias,
                                              float* __restrict__ C, int ldc, int K,
                                              float scale) {
    __shared__ float As[32][65];
    __shared__ float Bs[32][64];
    int tid = threadIdx.x;
    int m0 = blockIdx.x * 64;
    int n0 = blockIdx.y * 64;
    int ty = tid >> 4, tx = tid & 15;

    float acc[4][4];
#pragma unroll
    for (int i = 0; i < 4; i++)
#pragma unroll
        for (int j = 0; j < 4; j++) acc[i][j] = 0.f;

    for (int k0 = 0; k0 < K; k0 += 32) {
#pragma unroll
        for (int i = 0; i < 8; i++) {
            int e = (i << 8) + tid;
            int r = e >> 5, c = e & 31;
            As[c][r] = A[(size_t)(m0 + r) * lda + k0 + c];
        }
#pragma unroll
        for (int i = 0; i < 8; i++) {
            int e = (i << 8) + tid;
            int r = e >> 6, c = e & 63;
            Bs[r][c] = B[(size_t)(k0 + r) * ldb + n0 + c];
        }
        __syncthreads();
#pragma unroll
        for (int kk = 0; kk < 32; kk++) {
            float4 bv = *reinterpret_cast<const float4*>(&Bs[kk][tx << 2]);
            float a0 = As[kk][(ty << 2) + 0];
            float a1 = As[kk][(ty << 2) + 1];
            float a2 = As[kk][(ty << 2) + 2];
            float a3 = As[kk][(ty << 2) + 3];
            acc[0][0] = fmaf(a0, bv.x, acc[0][0]); acc[0][1] = fmaf(a0, bv.y, acc[0][1]);
            acc[0][2] = fmaf(a0, bv.z, acc[0][2]); acc[0][3] = fmaf(a0, bv.w, acc[0][3]);
            acc[1][0] = fmaf(a1, bv.x, acc[1][0]); acc[1][1] = fmaf(a1, bv.y, acc[1][1]);
            acc[1][2] = fmaf(a1, bv.z, acc[1][2]); acc[1][3] = fmaf(a1, bv.w, acc[1][3]);
            acc[2][0] = fmaf(a2, bv.x, acc[2][0]); acc[2][1] = fmaf(a2, bv.y, acc[2][1]);
            acc[2][2] = fmaf(a2, bv.z, acc[2][2]); acc[2][3] = fmaf(a2, bv.w, acc[2][3]);
            acc[3][0] = fmaf(a3, bv.x, acc[3][0]); acc[3][1] = fmaf(a3, bv.y, acc[3][1]);
            acc[3][2] = fmaf(a3, bv.z, acc[3][2]); acc[3][3] = fmaf(a3, bv.w, acc[3][3]);
        }
        __syncthreads();
    }

    float bv[4] = {0.f, 0.f, 0.f, 0.f};
    if (bias) {
#pragma unroll
        for (int j = 0; j < 4; j++) bv[j] = bias[n0 + (tx << 2) + j];
    }
#pragma unroll
    for (int i = 0; i < 4; i++) {
        float* cp = C + (size_t)(m0 + (ty << 2) + i) * ldc + n0 + (tx << 2);
#pragma unroll
        for (int j = 0; j < 4; j++) cp[j] = fmaf(scale, acc[i][j], bv[j]);
    }
}

// ---------------- gemm128w: 512 threads, FFMA2 micro-kernel, N=128, K mult 16 ----------------
// C = scale * A @ B; dual-problem select via blockIdx.y.
__global__ void __launch_bounds__(512) gemm128w(const float* __restrict__ A, int lda,
                                                const float* __restrict__ B0,
                                                const float* __restrict__ B1,
                                                float* __restrict__ C0v,
                                                float* __restrict__ C1v,
                                                int K, float scale) {
    __shared__ float As[16][132];
    __shared__ float Bs[16][128];
    int tid = threadIdx.x;
    int m0 = blockIdx.x * 128;
    const float* B = (blockIdx.y == 0) ? B0 : B1;
    float* C = (blockIdx.y == 0) ? C0v : C1v;
    int ty = tid >> 4;      // 0..31 -> 4-row group
    int tx = tid & 15;      // 0..15 -> 8-col group (4 packed pairs)

    uint64_t acc2[4][4];
#pragma unroll
    for (int i = 0; i < 4; i++)
#pragma unroll
        for (int j = 0; j < 4; j++) acc2[i][j] = pack2(0.f, 0.f);

    for (int k0 = 0; k0 < K; k0 += 16) {
        {   // A: 128 rows x 16 k -> As[k][row]; one float4 per thread
            int r = tid >> 2, c4 = tid & 3;
            float4 va = *reinterpret_cast<const float4*>(
                A + (size_t)(m0 + r) * lda + k0 + (c4 << 2));
            As[(c4 << 2) + 0][r] = va.x;
            As[(c4 << 2) + 1][r] = va.y;
            As[(c4 << 2) + 2][r] = va.z;
            As[(c4 << 2) + 3][r] = va.w;
        }
        {   // B: 16 k x 128 cols; one float4 per thread
            int r = tid >> 5, c4 = tid & 31;
            reinterpret_cast<float4*>(Bs[r])[c4] =
                *reinterpret_cast<const float4*>(B + (size_t)(k0 + r) * 128 + (c4 << 2));
        }
        __syncthreads();
#pragma unroll
        for (int kk = 0; kk < 16; kk++) {
            const uint64_t* bp = reinterpret_cast<const uint64_t*>(&Bs[kk][tx << 3]);
            uint64_t bq0 = bp[0], bq1 = bp[1], bq2 = bp[2], bq3 = bp[3];
            float a0 = As[kk][(ty << 2) + 0];
            float a1 = As[kk][(ty << 2) + 1];
            float a2 = As[kk][(ty << 2) + 2];
            float a3 = As[kk][(ty << 2) + 3];
            uint64_t aq0 = pack2(a0, a0), aq1 = pack2(a1, a1);
            uint64_t aq2 = pack2(a2, a2), aq3 = pack2(a3, a3);
            FMA2(acc2[0][0], aq0, bq0, acc2[0][0]); FMA2(acc2[0][1], aq0, bq1, acc2[0][1]);
            FMA2(acc2[0][2], aq0, bq2, acc2[0][2]); FMA2(acc2[0][3], aq0, bq3, acc2[0][3]);
            FMA2(acc2[1][0], aq1, bq0, acc2[1][0]); FMA2(acc2[1][1], aq1, bq1, acc2[1][1]);
            FMA2(acc2[1][2], aq1, bq2, acc2[1][2]); FMA2(acc2[1][3], aq1, bq3, acc2[1][3]);
            FMA2(acc2[2][0], aq2, bq0, acc2[2][0]); FMA2(acc2[2][1], aq2, bq1, acc2[2][1]);
            FMA2(acc2[2][2], aq2, bq2, acc2[2][2]); FMA2(acc2[2][3], aq2, bq3, acc2[2][3]);
            FMA2(acc2[3][0], aq3, bq0, acc2[3][0]); FMA2(acc2[3][1], aq3, bq1, acc2[3][1]);
            FMA2(acc2[3][2], aq3, bq2, acc2[3][2]); FMA2(acc2[3][3], aq3, bq3, acc2[3][3]);
        }
        __syncthreads();
    }

#pragma unroll
    for (int i = 0; i < 4; i++) {
        float* cp = C + (size_t)(m0 + (ty << 2) + i) * 128 + (tx << 3);
        float2 p0 = upk(acc2[i][0]), p1 = upk(acc2[i][1]);
        float2 p2 = upk(acc2[i][2]), p3 = upk(acc2[i][3]);
        *reinterpret_cast<float4*>(cp) =
            make_float4(scale * p0.x, scale * p0.y, scale * p1.x, scale * p1.y);
        *reinterpret_cast<float4*>(cp + 4) =
            make_float4(scale * p2.x, scale * p2.y, scale * p3.x, scale * p3.y);
    }
}

// ---------------- GRU: FFMA2 packed dot, parallel activation ----------------
__global__ void __launch_bounds__(384) k_gru(const float* __restrict__ Whh,
                                             const float* __restrict__ bhh,
                                             const float* __restrict__ h0) {
    __shared__ float hs[2][128];
    __shared__ float gh[2][384];
    __shared__ float sA0[384], sA1[384], sC0[384];
    __shared__ float2 sXY[2];
    int j = threadIdx.x;
    int b0 = blockIdx.x * 2, b1 = b0 + 1;

    uint64_t wq[64];
    {
        const ulonglong2* Wq = reinterpret_cast<const ulonglong2*>(Whh + (size_t)j * 128);
#pragma unroll
        for (int i = 0; i < 32; i++) { ulonglong2 v = Wq[i]; wq[2*i] = v.x; wq[2*i+1] = v.y; }
    }
    float bj = bhh[j];
    sA0[j] = g_A0[j]; sA1[j] = g_A1[j]; sC0[j] = g_C0[j];
    if (j < 128) {
        hs[0][j] = h0[b0 * 128 + j];
        hs[1][j] = h0[b1 * 128 + j];
    }
    __syncthreads();

    for (int t = 0; t < TT; t++) {
        uint64_t a0 = 0ull, a1 = 0ull, a2 = 0ull, a3 = 0ull;
        const ulonglong2* h0q = reinterpret_cast<const ulonglong2*>(hs[0]);
        const ulonglong2* h1q = reinterpret_cast<const ulonglong2*>(hs[1]);
#pragma unroll
        for (int i = 0; i < 32; i++) {
            ulonglong2 x = h0q[i], y = h1q[i];
            FMA2(a0, wq[2*i],   x.x, a0);
            FMA2(a1, wq[2*i+1], x.y, a1);
            FMA2(a2, wq[2*i],   y.x, a2);
            FMA2(a3, wq[2*i+1], y.y, a3);
        }
        float2 u0 = upk(a0), u1 = upk(a1), u2 = upk(a2), u3 = upk(a3);
        gh[0][j] = (u0.x + u0.y) + (u1.x + u1.y) + bj;
        gh[1][j] = (u2.x + u2.y) + (u3.x + u3.y) + bj;
        if (j < 2) sXY[j] = g_XY[t * 256 + b0 + j];
        __syncthreads();
        if (j < 256) {
            int r = j >> 7, jj = j & 127;
            int bb = b0 + r;
            float x0 = sXY[r].x, x1 = sXY[r].y;
            float gi0 = fmaf(x0, sA0[jj],       fmaf(x1, sA1[jj],       sC0[jj]));
            float gi1 = fmaf(x0, sA0[128 + jj], fmaf(x1, sA1[128 + jj], sC0[128 + jj]));
            float gi2 = fmaf(x0, sA0[256 + jj], fmaf(x1, sA1[256 + jj], sC0[256 + jj]));
            float rg = sigmoid_f(gi0 + gh[r][jj]);
            float zg = sigmoid_f(gi1 + gh[r][128 + jj]);
            float ng = tanh_f(fmaf(rg, gh[r][256 + jj], gi2));
            float hn = fmaf(zg, hs[r][jj] - ng, ng);
            hs[r][jj] = hn;
            g_Hall[(size_t)(t * 256 + bb) * 128 + jj] = hn;
        }
        __syncthreads();
    }
}

// ---------------- attention: warp per (b, t-pair), packed f32x2 ----------------
__global__ void __launch_bounds__(512) k_attn(const float* __restrict__ ih,
                                              const float* __restrict__ v_a) {
    extern __shared__ float dyn[];
    float* sPAT = dyn;
    float* sIH  = dyn + 16384;
    float* sHW  = dyn + 32768;
    float* sVAn = dyn + 36864;
    float* sAT  = dyn + 36992;
    int tid = threadIdx.x;
    int wid = tid >> 5, l = tid & 31;
    int b0 = blockIdx.x * 2;

    {
        int s = tid & 63, kq = tid >> 6;
#pragma unroll
        for (int bh = 0; bh < 2; bh++) {
            const float* src = g_PA + (size_t)(b0 + bh) * 8192 + s * 128;
            float* dst = sPAT + bh * 8192;
#pragma unroll
            for (int i = 0; i < 4; i++) {
                int k4 = kq + (i << 3);
                float4 v = *reinterpret_cast<const float4*>(src + (k4 << 2));
                dst[((k4 << 2) + 0) * 64 + s] = fminf(v.x, 40.f);
                dst[((k4 << 2) + 1) * 64 + s] = fminf(v.y, 40.f);
                dst[((k4 << 2) + 2) * 64 + s] = fminf(v.z, 40.f);
                dst[((k4 << 2) + 3) * 64 + s] = fminf(v.w, 40.f);
            }
        }
        for (int i = tid; i < 4096; i += 512) {
            int bh = i >> 11, e = i & 2047;
            reinterpret_cast<float4*>(sIH + bh * 8192)[e] =
                reinterpret_cast<const float4*>(ih + (size_t)(b0 + bh) * 8192)[e];
        }
        if (tid < 128) sVAn[tid] = -v_a[tid];
    }
    __syncthreads();
    float vs = g_VAS[0];
    const uint64_t two2 = pack2(2.0f, 2.0f);

    for (int u = wid; u < 64; u += 16) {
        int bh = u >> 5, q = u & 31;
        int t1 = q * 2;
        int t2 = min(q * 2 + 1, 62);
        int b = b0 + bh;

        float2* hwp = reinterpret_cast<float2*>(sHW + wid * 256);
        {
            const float* g1 = g_HA2 + (size_t)(t1 * 256 + b) * 128;
            const float* g2 = g_HA2 + (size_t)(t2 * 256 + b) * 128;
#pragma unroll
            for (int c = 0; c < 4; c++) {
                int k = l + (c << 5);
                hwp[k] = make_float2(fminf(__ldg(g1 + k), 40.f),
                                     fminf(__ldg(g2 + k), 40.f));
            }
        }
        __syncwarp();

        const float* pat = sPAT + bh * 8192;
        uint64_t accA = pack2(0.f, 0.f), accB = accA;
#pragma unroll 8
        for (int k = 0; k < 128; k++) {
            uint64_t p2q = *reinterpret_cast<const uint64_t*>(pat + (k << 6) + (l << 1));
            float2 yv = hwp[k];
            float van = sVAn[k];
            uint64_t van2 = pack2(van, van);
            uint64_t y1q = pack2(yv.x, yv.x), y2q = pack2(yv.y, yv.y);
            uint64_t aA, aB;
            ADD2(aA, p2q, y1q); ADD2(aB, p2q, y2q);
            term2(aA, van2, two2, accA);
            term2(aB, van2, two2, accB);
        }
        float2 uA = upk(accA), uB = upk(accB);
        float sc11 = fmaf(-2.f, uA.x, vs), sc12 = fmaf(-2.f, uA.y, vs);
        float sc21 = fmaf(-2.f, uB.x, vs), sc22 = fmaf(-2.f, uB.y, vs);

        float a10, a11v, a20, a21v;
        {
            float mx = fmaxf(sc11, sc12);
#pragma unroll
            for (int o = 16; o; o >>= 1) mx = fmaxf(mx, __shfl_xor_sync(0xFFFFFFFFu, mx, o));
            float e0 = __expf(sc11 - mx), e1 = __expf(sc12 - mx);
            float sm = warp_sum(e0 + e1);
            float inv = rcpf(sm);
            a10 = e0 * inv; a11v = e1 * inv;
        }
        {
            float mx = fmaxf(sc21, sc22);
#pragma unroll
            for (int o = 16; o; o >>= 1) mx = fmaxf(mx, __shfl_xor_sync(0xFFFFFFFFu, mx, o));
            float e0 = __expf(sc21 - mx), e1 = __expf(sc22 - mx);
            float sm = warp_sum(e0 + e1);
            float inv = rcpf(sm);
            a20 = e0 * inv; a21v = e1 * inv;
        }
        float* atw = sAT + wid * 128;
        reinterpret_cast<float4*>(atw)[l] = make_float4(a10, a20, a11v, a21v);
        __syncwarp();

        const float2* atp = reinterpret_cast<const float2*>(atw);
        const float* ihb = sIH + bh * 8192;
        uint64_t c1xy = pack2(0.f, 0.f), c1zw = c1xy, c2xy = c1xy, c2zw = c1xy;
#pragma unroll 8
        for (int s = 0; s < 64; s++) {
            float2 ap = atp[s];
            float4 v = *reinterpret_cast<const float4*>(ihb + (s << 7) + (l << 2));
            uint64_t vxy = pack2(v.x, v.y), vzw = pack2(v.z, v.w);
            uint64_t a1q = pack2(ap.x, ap.x), a2q = pack2(ap.y, ap.y);
            FMA2(c1xy, a1q, vxy, c1xy); FMA2(c1zw, a1q, vzw, c1zw);
            FMA2(c2xy, a2q, vxy, c2xy); FMA2(c2zw, a2q, vzw, c2zw);
        }
        float2 p1 = upk(c1xy), p2v = upk(c1zw), p3 = upk(c2xy), p4 = upk(c2zw);
        *reinterpret_cast<float4*>(g_CTX + (size_t)(t1 * 256 + b) * 128 + (l << 2)) =
            make_float4(p1.x, p1.y, p2v.x, p2v.y);
        *reinterpret_cast<float4*>(g_CTX + (size_t)(t2 * 256 + b) * 128 + (l << 2)) =
            make_float4(p3.x, p3.y, p4.x, p4.y);
        __syncwarp();
    }
}

// ---------------- pointer: warp per (b, t-pair), packed f32x2 ----------------
__global__ void __launch_bounds__(512) k_ptr(const int* __restrict__ sol,
                                             const float* __restrict__ vp,
                                             float* __restrict__ out) {
    extern __shared__ float dyn[];
    float*  sPPT = dyn;
    float*  sFW  = dyn + 16384;
    float*  sVPn = dyn + 20480;
    float*  sZB  = dyn + 20608;
    float*  sE0  = dyn + 20864;
    float*  sE1  = dyn + 20992;
    float2* sXY  = reinterpret_cast<float2*>(dyn + 21120);
    int*    sPos = reinterpret_cast<int*>(dyn + 21376);
    int*    sSol = reinterpret_cast<int*>(dyn + 21504);
    int tid = threadIdx.x;
    int wid = tid >> 5, l = tid & 31;
    int b0 = blockIdx.x * 2;

    {
        int s = tid & 63, kq = tid >> 6;
#pragma unroll
        for (int bh = 0; bh < 2; bh++) {
            const float* src = g_PP + (size_t)(b0 + bh) * 8192 + s * 128;
            float* dst = sPPT + bh * 8192;
#pragma unroll
            for (int i = 0; i < 4; i++) {
                int k4 = kq + (i << 3);
                float4 v = *reinterpret_cast<const float4*>(src + (k4 << 2));
                dst[((k4 << 2) + 0) * 64 + s] = fminf(v.x, 40.f);
                dst[((k4 << 2) + 1) * 64 + s] = fminf(v.y, 40.f);
                dst[((k4 << 2) + 2) * 64 + s] = fminf(v.z, 40.f);
                dst[((k4 << 2) + 3) * 64 + s] = fminf(v.w, 40.f);
            }
        }
        if (tid < 128) sVPn[tid] = -vp[tid];
        if (tid >= 128 && tid < 160) {
            int i = tid - 128;
            reinterpret_cast<float4*>(sE0)[i] = reinterpret_cast<const float4*>(g_E0)[i];
        }
        if (tid >= 160 && tid < 192) {
            int i = tid - 160;
            reinterpret_cast<float4*>(sE1)[i] = reinterpret_cast<const float4*>(g_E1)[i];
        }
        if (tid >= 192 && tid < 256) {
            int i = tid - 192;
            reinterpret_cast<float4*>(sZB)[i] =
                reinterpret_cast<const float4*>(g_ZB + b0 * 128)[i];
        }
        if (tid >= 256 && tid < 382) {
            int i = tid - 256;
            int bh = i & 1, t = i >> 1;
            sXY[bh * 64 + t] = g_XY[t * 256 + b0 + bh];
        }
        if (tid >= 384 && tid < 512) {
            int i = tid - 384;
            int bh = i >> 6;
            sPos[i] = g_pos[(b0 + bh) * 64 + (i & 63)];
            sSol[i] = sol[(b0 + bh) * 64 + (i & 63)];
        }
    }
    __syncthreads();
    float vps = g_VPS[0];
    const uint64_t two2 = pack2(2.0f, 2.0f);

    for (int u = wid; u < 64; u += 16) {
        int bh = u >> 5, q = u & 31;
        int t1 = q * 2;
        int t2 = min(q * 2 + 1, 62);
        int b = b0 + bh;

        float2* fwp = reinterpret_cast<float2*>(sFW + wid * 256);
        {
            float2 xy1 = sXY[bh * 64 + t1];
            float2 xy2 = sXY[bh * 64 + t2];
            const float* gf1 = g_FP2 + (size_t)(t1 * 256 + b) * 128;
            const float* gf2 = g_FP2 + (size_t)(t2 * 256 + b) * 128;
#pragma unroll
            for (int c = 0; c < 4; c++) {
                int k = l + (c << 5);
                float zb = sZB[bh * 128 + k], e0 = sE0[k], e1 = sE1[k];
                float f1 = __ldg(gf1 + k) + zb + xy1.x * e0 + xy1.y * e1;
                float f2 = __ldg(gf2 + k) + zb + xy2.x * e0 + xy2.y * e1;
                fwp[k] = make_float2(fminf(f1, 40.f), fminf(f2, 40.f));
            }
        }
        __syncwarp();

        const float* ppt = sPPT + bh * 8192;
        uint64_t accA = pack2(0.f, 0.f), accB = accA;
#pragma unroll 8
        for (int k = 0; k < 128; k++) {
            uint64_t p2q = *reinterpret_cast<const uint64_t*>(ppt + (k << 6) + (l << 1));
            float2 yv = fwp[k];
            float van = sVPn[k];
            uint64_t van2 = pack2(van, van);
            uint64_t y1q = pack2(yv.x, yv.x), y2q = pack2(yv.y, yv.y);
            uint64_t aA, aB;
            ADD2(aA, p2q, y1q); ADD2(aB, p2q, y2q);
            term2(aA, van2, two2, accA);
            term2(aB, van2, two2, accB);
        }
        float2 uA = upk(accA), uB = upk(accB);
        float sc11 = fmaf(-2.f, uA.x, vps), sc12 = fmaf(-2.f, uA.y, vps);
        float sc21 = fmaf(-2.f, uB.x, vps), sc22 = fmaf(-2.f, uB.y, vps);

        int pos_a = sPos[bh * 64 + (l << 1)];
        int pos_b = sPos[bh * 64 + (l << 1) + 1];

#pragma unroll
        for (int pass = 0; pass < 2; pass++) {
            int t = pass ? t2 : t1;
            float scA = pass ? sc21 : sc11;
            float scB = pass ? sc22 : sc12;
            float v0 = (pos_a > t) ? scA : -3.0e38f;
            float v1 = (pos_b > t) ? scB : -3.0e38f;
            float bv; int bi;
            if (v0 >= v1) { bv = v0; bi = (l << 1); } else { bv = v1; bi = (l << 1) + 1; }
#pragma unroll
            for (int o = 16; o; o >>= 1) {
                float ov = __shfl_xor_sync(0xFFFFFFFFu, bv, o);
                int   oi = __shfl_xor_sync(0xFFFFFFFFu, bi, o);
                if (ov > bv || (ov == bv && oi < bi)) { bv = ov; bi = oi; }
            }
            float e0 = (v0 > -1.0e38f) ? __expf(v0 - bv) : 0.f;
            float e1 = (v1 > -1.0e38f) ? __expf(v1 - bv) : 0.f;
            float sm = warp_sum(e0 + e1);

            int ptr = sSol[bh * 64 + t + 1];
            float lpa = __shfl_sync(0xFFFFFFFFu, scA, ptr >> 1);
            float lpb = __shfl_sync(0xFFFFFFFFu, scB, ptr >> 1);
            float lraw = (ptr & 1) ? lpb : lpa;
            if (l == 0) {
                out[(b << 6) + t + 1] = (float)bi;
                out[16384 + b * 63 + t] = lraw - bv - logf(sm);
            }
        }
    }
}

// ---------------- launch ----------------
extern "C" void kernel_launch(void* const* d_in, const int* in_sizes, int n_in,
                              void* d_out, int out_size) {
    const float* instance = (const float*)d_in[0];
    const int*   sol      = (const int*)  d_in[1];
    const float* Z        = (const float*)d_in[2];
    const float* ih       = (const float*)d_in[3];
    const float* h0       = (const float*)d_in[4];
    const float* W_emb    = (const float*)d_in[5];
    const float* b_emb    = (const float*)d_in[6];
    const float* W_ih     = (const float*)d_in[7];
    const float* W_hh     = (const float*)d_in[8];
    const float* b_ih     = (const float*)d_in[9];
    const float* b_hh     = (const float*)d_in[10];
    const float* W_a      = (const float*)d_in[11];
    const float* v_a      = (const float*)d_in[12];
    const float* W1       = (const float*)d_in[13];
    const float* b1       = (const float*)d_in[14];
    const float* W2       = (const float*)d_in[15];
    const float* b2       = (const float*)d_in[16];
    const float* Wp       = (const float*)d_in[17];
    const float* vp       = (const float*)d_in[18];
    float* out = (float*)d_out;
    (void)in_sizes; (void)n_in; (void)out_size; (void)b2;

    float *pPA, *pPP, *pHall, *pHA2, *pCTX, *pFP2, *pZB, *pW12, *pWc, *pZBIAS;
    cudaGetSymbolAddress((void**)&pPA,    g_PA);
    cudaGetSymbolAddress((void**)&pPP,    g_PP);
    cudaGetSymbolAddress((void**)&pHall,  g_Hall);
    cudaGetSymbolAddress((void**)&pHA2,   g_HA2);
    cudaGetSymbolAddress((void**)&pCTX,   g_CTX);
    cudaGetSymbolAddress((void**)&pFP2,   g_FP2);
    cudaGetSymbolAddress((void**)&pZB,    g_ZB);
    cudaGetSymbolAddress((void**)&pW12,   g_W12);
    cudaGetSymbolAddress((void**)&pWc,    g_Wc);
    cudaGetSymbolAddress((void**)&pZBIAS, g_ZBIAS);

    static cudaStream_t s1 = nullptr, s2 = nullptr;
    static cudaEvent_t evF = nullptr, evA = nullptr, evPP = nullptr, evZB = nullptr;
    if (s1 == nullptr) {
        cudaStreamCreateWithFlags(&s1, cudaStreamNonBlocking);
        cudaStreamCreateWithFlags(&s2, cudaStreamNonBlocking);
        cudaEventCreateWithFlags(&evF,  cudaEventDisableTiming);
        cudaEventCreateWithFlags(&evA,  cudaEventDisableTiming);
        cudaEventCreateWithFlags(&evPP, cudaEventDisableTiming);
        cudaEventCreateWithFlags(&evZB, cudaEventDisableTiming);
        cudaFuncSetAttribute(k_attn, cudaFuncAttributeMaxDynamicSharedMemorySize, 164 * 1024);
        cudaFuncSetAttribute(k_ptr,  cudaFuncAttributeMaxDynamicSharedMemorySize, 92 * 1024);
    }

    cudaEventRecord(evF, 0);
    cudaStreamWaitEvent(s1, evF, 0);
    cudaStreamWaitEvent(s2, evF, 0);

    // s2: PA/PP (scaled by C2E), FFMA2 GEMM
    gemm128w<<<dim3(128, 2), 512, 0, s2>>>(ih, 128, W_a, Wp, pPA, pPP, 128, C2E);
    cudaEventRecord(evPP, s2);

    // main: merged init + prep1
    k_initprep<<<193, 256>>>(instance, sol, out, W_emb, b_emb, W_ih, b_ih, b1, W2, v_a, vp);
    cudaEventRecord(evA, 0);

    // s1: W12, Wc, prep2, ZB
    gemm64<<<dim3(6, 2), 256, 0, s1>>>(W1, 256, W2, 128, nullptr, pW12, 128, 256, 1.0f);
    gemm64<<<dim3(6, 2), 256, 0, s1>>>(pW12, 128, Wp + 128 * 128, 128, nullptr, pWc, 128, 128, 1.0f);
    cudaStreamWaitEvent(s1, evA, 0);
    k_prep2<<<48, 256, 0, s1>>>(W_emb, b_emb, Wp);
    gemm64<<<dim3(4, 2), 256, 0, s1>>>(Z, 128, pWc + 128 * 128, 128, pZBIAS, pZB, 128, 128, C2E);
    cudaEventRecord(evZB, s1);

    // main: GRU, HA2 (FFMA2 GEMM)
    k_gru<<<128, 384>>>(W_hh, b_hh, h0);
    gemm128w<<<dim3(126, 1), 512>>>(pHall, 128, W_a + 128 * 128, nullptr, pHA2, nullptr, 128, C2E);

    cudaStreamWaitEvent(0, evPP, 0);
    k_attn<<<128, 512, 39040 * 4>>>(ih, v_a);

    // FP2 = CTX @ Wc[:128] (FFMA2 GEMM)
    gemm128w<<<dim3(126, 1), 512>>>(pCTX, 128, pWc, nullptr, pFP2, nullptr, 128, C2E);

    cudaStreamWaitEvent(0, evZB, 0);
    k_ptr<<<128, 512, 21632 * 4>>>(sol, vp, out);
}